// round 9
// baseline (speedup 1.0000x reference)
#include <cuda_runtime.h>
#include <cstdint>

#define TT 256
#define HH 512
#define BB 128
#define NGATE 2048
#define GRID 128
#define NTHR 512
#define NKC 8
#define LDSD 136               // padded row stride (floats) -> conflict-free frags
#define CH_FL (128*LDSD)       // floats per full 128-row chunk  (17408)
#define STG_FL (64*LDSD)       // floats per CTA chunk slab      (8704)
#define STG_BY (STG_FL*4)      // 34816 B
#define SMEMB 118784           // 3 stages (104448) + pad

#define O_H1F 16777216L
#define O_M0  16908288L
#define O_M1F 33685504L

// ---------------- device scratch ----------------
// W fragment order: [cell(2)][n0b(5)][kc(3)][wn4(2)][ks(4)][lane(5)][j(1)][p(1)]
__device__ __align__(16) float g_Wf[8388608L];
__device__ __align__(16) float g_bias[4][NGATE];
// chunk-major padded A sources: [kc][m(128)][136]
__device__ __align__(16) float g_H0r[(long)TT*4*CH_FL];     // [t][kc][m][136]
__device__ __align__(16) float g_h1r[2][2][4*CH_FL];        // [layer][parity]
__device__ __align__(16) float g_h0ar[4*CH_FL];
__device__ __align__(16) float g_h0br[4*CH_FL];
// linear full-precision state
__device__ __align__(16) float g_h1f[2][BB*HH];
__device__ __align__(16) float g_m1[2][BB*HH];
__device__ __align__(16) float g_m0a[BB*HH];
__device__ unsigned g_cnt;
__device__ volatile unsigned g_gen;

// ---------------- helpers ----------------
__device__ __forceinline__ float tf32f(float x) {
    unsigned u; asm("cvt.rna.tf32.f32 %0, %1;" : "=r"(u) : "f"(x));
    return __uint_as_float(u);
}
__device__ __forceinline__ float sigf(float x) { return 1.f / (1.f + __expf(-x)); }

__device__ __forceinline__ void mma8(float* c, const unsigned* a, unsigned b0, unsigned b1) {
    asm volatile(
        "mma.sync.aligned.m16n8k8.row.col.f32.tf32.tf32.f32 "
        "{%0,%1,%2,%3}, {%4,%5,%6,%7}, {%8,%9}, {%0,%1,%2,%3};"
        : "+f"(c[0]), "+f"(c[1]), "+f"(c[2]), "+f"(c[3])
        : "r"(a[0]), "r"(a[1]), "r"(a[2]), "r"(a[3]), "r"(b0), "r"(b1));
}

__device__ __forceinline__ void mbwait(uint32_t mbar, unsigned par) {
    asm volatile(
        "{\n\t.reg .pred P;\n\t"
        "W%=:\n\t"
        "mbarrier.try_wait.parity.shared.b64 P, [%0], %1;\n\t"
        "@!P bra W%=;\n\t}"
        :: "r"(mbar), "r"(par) : "memory");
}

// one bulk copy: 64 rows x 136 floats (34816 B) -> smem stage  (tid 0 only)
__device__ __forceinline__ void ldbulk(uint32_t sb, uint32_t mb0, int st, int kc,
                                       const float* xq, const float* hq)
{
    const float* src = (kc < 4) ? (xq + (long)kc * CH_FL) : (hq + (long)(kc - 4) * CH_FL);
    uint32_t dst = sb + (uint32_t)st * STG_BY;
    uint32_t mb = mb0 + st * 8;
    asm volatile("mbarrier.arrive.expect_tx.shared.b64 _, [%0], %1;"
                 :: "r"(mb), "r"(STG_BY) : "memory");
    asm volatile("cp.async.bulk.shared::cluster.global.mbarrier::complete_tx::bytes "
                 "[%0], [%1], %2, [%3];"
                 :: "r"(dst), "l"(src), "r"(STG_BY), "r"(mb) : "memory");
}

// grid barrier: 128 CTAs <= 148 SMs, all resident -> deadlock-free
__device__ __forceinline__ void gsync() {
    __threadfence();
    __syncthreads();
    if (threadIdx.x == 0) {
        unsigned g = g_gen;
        if (atomicAdd(&g_cnt, 1u) == GRID - 1) {
            g_cnt = 0;
            __threadfence();
            g_gen = g + 1;
        } else {
            while (g_gen == g) { }
        }
    }
    __syncthreads();
    __threadfence();
}

// one LSTM cell tile: gates[64 x 64] = [x;h] @ W^T + b, then elementwise.
// xq/hq/hrd: chunk-major slabs pre-offset by m0*136. cold/hfull/cdst: linear, pre-offset.
__device__ __noinline__ void cell_run(uint32_t sb, float* smf, uint32_t mb0, unsigned* mpar,
    int n0,
    const float* xq, const float* hq,
    const float* bias_n0,
    const float* cold,
    float* hfull, long hfs, float* hrd, float* cdst, long cds,
    const float* wbase)
{
    int tid = threadIdx.x, w = tid >> 5, lane = tid & 31;
    int rb = lane >> 2, q = lane & 3;
    int wm = (w & 3) * 16;
    int wn4 = w >> 2;
    int wn = wn4 * 16;

    float acc[2][4];
    #pragma unroll
    for (int j = 0; j < 2; ++j)
        #pragma unroll
        for (int v = 0; v < 4; ++v) acc[j][v] = 0.f;

    float4 bA[8], bB[8];
    const float4* wlane4 = (const float4*)wbase + wn4 * 512 + lane;

    // W half-chunk loader: half h of chunk kc -> buf (8 x LDG.128)
    #define LOADB(buf, kc_, h_) do {                                           \
        const float4* wp_ = wlane4 + (kc_) * 2048;                             \
        _Pragma("unroll")                                                      \
        for (int ks_ = 0; ks_ < 8; ++ks_)                                      \
            (buf)[ks_] = wp_[(((h_) * 8 + ks_)) * 32];                         \
    } while (0)

    #define COMP8(buf, Ab_, ksb_) do {                                         \
        const float* ap_ = (Ab_) + (wm + rb) * LDSD + 2 * q + (ksb_) * 8;      \
        _Pragma("unroll")                                                      \
        for (int ks_ = 0; ks_ < 8; ++ks_) {                                    \
            unsigned a_[4];                                                    \
            float2 lo_ = *(const float2*)(ap_ + ks_ * 8);                      \
            float2 hi_ = *(const float2*)(ap_ + 8 * LDSD + ks_ * 8);           \
            a_[0] = __float_as_uint(lo_.x);                                    \
            a_[1] = __float_as_uint(hi_.x);                                    \
            a_[2] = __float_as_uint(lo_.y);                                    \
            a_[3] = __float_as_uint(hi_.y);                                    \
            float4 bv_ = (buf)[ks_];                                           \
            mma8(acc[0], a_, __float_as_uint(bv_.x), __float_as_uint(bv_.y));  \
            mma8(acc[1], a_, __float_as_uint(bv_.z), __float_as_uint(bv_.w));  \
        }                                                                      \
    } while (0)

    if (tid == 0) {
        ldbulk(sb, mb0, 0, 0, xq, hq);
        ldbulk(sb, mb0, 1, 1, xq, hq);
    }
    LOADB(bA, 0, 0);

    int st = 0;
    #pragma unroll 1
    for (int kc = 0; kc < NKC; ++kc) {
        __syncthreads();                         // all finished computing kc-1 (its stage now free)
        if (kc + 2 < NKC && tid == 0) {
            int s2 = st + 2; if (s2 >= 3) s2 -= 3;
            ldbulk(sb, mb0, s2, kc + 2, xq, hq);
        }
        mbwait(mb0 + st * 8, mpar[st] & 1);      // chunk kc data landed
        mpar[st]++;

        const float* Ab = smf + st * STG_FL;
        LOADB(bB, kc, 1);                        // prefetch 2nd half of this chunk's W
        COMP8(bA, Ab, 0);
        if (kc + 1 < NKC) LOADB(bA, kc + 1, 0);  // prefetch 1st half of next chunk's W
        COMP8(bB, Ab, 8);
        ++st; if (st >= 3) st -= 3;
    }
    #undef LOADB
    #undef COMP8

    // elementwise LSTM: gate cols 4u..4u+3 = (i,f,g,o) of unit u; pair lanes via shfl_xor 1
    bool ev = !(q & 1);
    #pragma unroll
    for (int j = 0; j < 2; ++j) {
        int ncl = wn + 8 * j + 2 * q;
        float b0 = bias_n0[ncl];
        float b1 = bias_n0[ncl + 1];
        #pragma unroll
        for (int h = 0; h < 2; ++h) {
            float v0 = acc[j][2 * h] + b0;
            float v1 = acc[j][2 * h + 1] + b1;
            float p0 = __shfl_xor_sync(0xffffffffu, v0, 1);
            float p1 = __shfl_xor_sync(0xffffffffu, v1, 1);
            if (ev) {
                float ig = v0, fg = v1, gg = p0, og = p1;
                int mrow = wm + rb + 8 * h;          // 0..63 local
                int u = (n0 + ncl) >> 2;              // 0..511
                float co = cold ? __ldcg(cold + (long)mrow * HH + u) : 0.f;
                float cn = sigf(fg) * co + sigf(ig) * tanhf(gg);
                float hn = sigf(og) * tanhf(cn);
                if (hfull) hfull[(long)mrow * hfs + u] = hn;
                int ub = u & 7;
                int up = (u & ~7) | ((ub < 4) ? 2 * ub : 2 * (ub - 4) + 1);  // forward k-permute
                hrd[(long)(up >> 7) * CH_FL + (long)mrow * LDSD + (up & 127)] = tf32f(hn);
                cdst[(long)mrow * cds + u] = cn;
            }
        }
    }
}

// ---------------- main persistent kernel ----------------
__global__ void __launch_bounds__(NTHR, 1) lstm_main(float* __restrict__ out) {
    extern __shared__ __align__(16) float smf[];
    __shared__ __align__(8) unsigned long long s_mbar[3];
    uint32_t sb = (uint32_t)__cvta_generic_to_shared(smf);
    uint32_t mb0 = (uint32_t)__cvta_generic_to_shared(&s_mbar[0]);

    int tid = threadIdx.x;
    int cta = blockIdx.x;
    int grp = cta >> 6;
    int c = cta & 63;
    int m0 = (c & 1) * 64;
    int n0b = c >> 1;
    int n0 = n0b * 64;
    const long TH = (long)TT * HH;
    long mo136 = (long)m0 * LDSD;
    long moH = (long)m0 * HH;
    long moT = (long)m0 * TH;

    if (tid == 0) {
        #pragma unroll
        for (int s = 0; s < 3; ++s)
            asm volatile("mbarrier.init.shared.b64 [%0], 1;" :: "r"(mb0 + s * 8) : "memory");
    }
    __syncthreads();

    unsigned mpar[3] = {0, 0, 0};

    const float* w0 = g_Wf + ((long)(0 * 32 + n0b)) * 65536;
    const float* w1 = g_Wf + ((long)(1 * 32 + n0b)) * 65536;
    const float* w2 = g_Wf + ((long)(2 * 32 + n0b)) * 65536;
    const float* w3 = g_Wf + ((long)(3 * 32 + n0b)) * 65536;

    #pragma unroll 1
    for (int ph = 0; ph <= 2 * TT; ++ph) {
        int t = ph >> 1;
        if (!(ph & 1)) {
            if (grp == 0) {
                if (t < TT)   // cell00(t): x=h1r[0], h=H0r[:,t], c=0 -> h0ar,m0a
                    cell_run(sb, smf, mb0, mpar, n0,
                             g_h1r[0][t & 1] + mo136,
                             g_H0r + (long)t * 4 * CH_FL + mo136,
                             &g_bias[0][n0], nullptr,
                             nullptr, 0, g_h0ar + mo136, g_m0a + moH, HH, w0);
            } else if (t >= 1) {  // cell11(t-1): x=h0br, h=h1r[1], c=m1[1]
                int tp = t - 1;
                cell_run(sb, smf, mb0, mpar, n0,
                         g_h0br + mo136, g_h1r[1][tp & 1] + mo136,
                         &g_bias[3][n0], g_m1[1] + moH,
                         g_h1f[1] + moH, HH, g_h1r[1][(tp + 1) & 1] + mo136,
                         g_m1[1] + moH, HH, w3);
            }
        } else {
            if (grp == 0) {       // cell01(t): x=h0ar, h=h1r[0], c=m1[0]
                cell_run(sb, smf, mb0, mpar, n0,
                         g_h0ar + mo136, g_h1r[0][t & 1] + mo136,
                         &g_bias[1][n0], g_m1[0] + moH,
                         g_h1f[0] + moH, HH, g_h1r[0][(t + 1) & 1] + mo136,
                         g_m1[0] + moH, HH, w1);
            } else {              // cell10(t): x=h1r[1], h=h0ar, c=m0a -> d_out + h0br
                cell_run(sb, smf, mb0, mpar, n0,
                         g_h1r[1][t & 1] + mo136, g_h0ar + mo136,
                         &g_bias[2][n0], g_m0a + moH,
                         out + moT + (long)t * HH, TH, g_h0br + mo136,
                         out + O_M0 + moT + (long)t * HH, TH, w2);
            }
        }
        gsync();
    }

    // final H1f / M1f
    for (long idx = (long)cta * NTHR + tid; idx < 2L * BB * HH; idx += (long)GRID * NTHR) {
        int b = (int)(idx >> 10), l = (int)((idx >> 9) & 1), j = (int)(idx & 511);
        out[O_H1F + idx] = __ldcg(&g_h1f[l][b * HH + j]);
        out[O_M1F + idx] = __ldcg(&g_m1[l][b * HH + j]);
    }
}

// ---------------- prep kernels ----------------
// W fragment order: f = [cell(2)][n0b(5)][kc(3)][wn4(2)][ks(4)][lane(5)][j(1)][p(1)]
__global__ void prep_wf(const float* __restrict__ Wih, const float* __restrict__ Whh) {
    long f = (long)blockIdx.x * blockDim.x + threadIdx.x;
    if (f >= 8388608L) return;
    int p    = (int)(f & 1);
    int j    = (int)((f >> 1) & 1);
    int lane = (int)((f >> 2) & 31);
    int ks   = (int)((f >> 7) & 15);
    int wn4  = (int)((f >> 11) & 3);
    int kc   = (int)((f >> 13) & 7);
    int n0b  = (int)((f >> 16) & 31);
    int cell = (int)(f >> 21);
    int rb = lane >> 2, q = lane & 3;
    int row = n0b * 64 + wn4 * 16 + j * 8 + rb;      // gate-interleaved: row = 4*unit + gate
    int g = row & 3, jj = row >> 2;
    long srow = (long)cell * NGATE + g * HH + jj;
    int k = kc * 128 + ks * 8 + q + p * 4;            // original k index
    float v = (k < HH) ? Wih[srow * HH + k] : Whh[srow * HH + (k - HH)];
    unsigned u; asm("cvt.rna.tf32.f32 %0, %1;" : "=r"(u) : "f"(v));
    g_Wf[f] = __uint_as_float(u);
}

// H0 [B][T][H] -> g_H0r [t][kc][m][136], FORWARD k-permute scatter + tf32 round.
// dest position for source feature h: hb<4 -> 2*hb ; hb>=4 -> 2*(hb-4)+1
__global__ void prep_x(const float* __restrict__ H0) {
    long i = (long)blockIdx.x * blockDim.x + threadIdx.x;
    if (i >= (long)BB * TT * HH) return;
    int h = (int)(i & 511);
    int t = (int)((i >> 9) & 255);
    int b = (int)(i >> 17);
    int hb = h & 7;
    int hp = (h & ~7) | ((hb < 4) ? 2 * hb : 2 * (hb - 4) + 1);
    int kc = hp >> 7, col = hp & 127;
    unsigned u; asm("cvt.rna.tf32.f32 %0, %1;" : "=r"(u) : "f"(H0[i]));
    g_H0r[((long)t * 4 + kc) * CH_FL + (long)b * LDSD + col] = __uint_as_float(u);
}

__global__ void prep_misc(const float* __restrict__ bih, const float* __restrict__ bhh) {
    long i = (long)blockIdx.x * blockDim.x + threadIdx.x;
    if (i < 2L * 2 * 4 * CH_FL) ((float*)g_h1r)[i] = 0.f;
    if (i < 2L * BB * HH) { ((float*)g_h1f)[i] = 0.f; ((float*)g_m1)[i] = 0.f; }
    if (i < 4 * NGATE) {
        int nr = (int)(i & 2047), cc = (int)(i >> 11);
        int g = nr & 3, j = nr >> 2;
        long s = (long)cc * NGATE + g * HH + j;
        ((float*)g_bias)[i] = bih[s] + bhh[s];
    }
    if (i == 0) { g_cnt = 0; g_gen = 0; }
}

// ---------------- launch ----------------
extern "C" void kernel_launch(void* const* d_in, const int* in_sizes, int n_in,
                              void* d_out, int out_size) {
    const float* H0  = (const float*)d_in[0];
    const float* Wih = (const float*)d_in[1];
    const float* Whh = (const float*)d_in[2];
    const float* bih = (const float*)d_in[3];
    const float* bhh = (const float*)d_in[4];
    float* out = (float*)d_out;

    prep_wf<<<32768, 256>>>(Wih, Whh);
    prep_x<<<65536, 256>>>(H0);
    prep_misc<<<2176, 256>>>(bih, bhh);

    cudaFuncSetAttribute(lstm_main, cudaFuncAttributeMaxDynamicSharedMemorySize, SMEMB);
    lstm_main<<<GRID, NTHR, SMEMB>>>(out);
}